// round 3
// baseline (speedup 1.0000x reference)
#include <cuda_runtime.h>

// Problem shape is fixed: depthin (1,1,480,640) float32, scalar float32 out.
#define ROWS 480
#define COLS 640
#define TH   16
#define TW   32
#define S    7
#define P    3
#define SMH  (TH + 2*P)   // 22
#define SMW  (TW + 2*P)   // 38
#define NBX  (COLS / TW)  // 20
#define NBY  (ROWS / TH)  // 30
#define NB   (NBX * NBY)  // 600

__device__ float g_blocksums[NB];

__device__ __forceinline__ float fsqrt_approx(float x) {
    float r;
    asm("sqrt.approx.f32 %0, %1;" : "=f"(r) : "f"(x));
    return r;
}

__global__ __launch_bounds__(TH * TW)
void stdev_kernel(const float* __restrict__ depth) {
    __shared__ float sz[SMH][SMW];

    const float inv_fx = (float)(1.0 / 582.6244816773795);
    const float inv_fy = (float)(1.0 / 582.6910327098864);
    const float cx = 313.0447587080473f;
    const float cy = 238.44389626620386f;

    const int bj0 = blockIdx.x * TW;
    const int bi0 = blockIdx.y * TH;
    const int tid = threadIdx.y * TW + threadIdx.x;

    // Cooperative load of the z tile (with ±3 halo). Halo cells outside the
    // image are clamped loads; they are never indexed by any clamped window.
    #pragma unroll
    for (int idx = tid; idx < SMH * SMW; idx += TH * TW) {
        int lr = idx / SMW, lc = idx % SMW;
        int gr = bi0 + lr - P; gr = min(max(gr, 0), ROWS - 1);
        int gc = bj0 + lc - P; gc = min(max(gc, 0), COLS - 1);
        float d = depth[gr * COLS + gc];
        sz[lr][lc] = (d > 0.0f && d < 1.01f) ? d * 1e-3f : 0.0f;
    }
    __syncthreads();

    const int i = bi0 + threadIdx.y;
    const int j = bj0 + threadIdx.x;

    // Clamped window start (matches reference's idif/jdif boundary shift).
    const int istart = min(max(i - P, 0), ROWS - S);
    const int jstart = min(max(j - P, 0), COLS - S);
    const int smr0 = istart - bi0 + P;   // in [0, SMH-S]
    const int smc0 = jstart - bj0 + P;   // in [0, SMW-S]

    const float z0 = sz[threadIdx.y + P][threadIdx.x + P];
    const float x0 = z0 * (((float)j - cx) * inv_fx);
    const float y0 = z0 * (((float)i - cy) * inv_fy);

    float cs[S], rs[S];
    #pragma unroll
    for (int t = 0; t < S; t++) cs[t] = ((float)(jstart + t) - cx) * inv_fx;
    #pragma unroll
    for (int s = 0; s < S; s++) rs[s] = ((float)(istart + s) - cy) * inv_fy;

    float sumd = 0.0f, sumsq = 0.0f;
    #pragma unroll
    for (int s = 0; s < S; s++) {
        #pragma unroll
        for (int t = 0; t < S; t++) {
            float zn = sz[smr0 + s][smc0 + t];
            float dx = fmaf(-zn, cs[t], x0);   // x0 - zn*colscale
            float dy = fmaf(-zn, rs[s], y0);   // y0 - zn*rowscale
            float dz = z0 - zn;
            float sq = fmaf(dx, dx, fmaf(dy, dy, dz * dz));
            sumd  += fsqrt_approx(sq);         // d
            sumsq += sq;                       // d^2 (exact, no extra sqrt)
        }
    }

    // Unbiased variance: (Σd² − (Σd)²/49) / 48
    float var = (sumsq - sumd * sumd * (1.0f / 49.0f)) * (1.0f / 48.0f);
    float dev = (z0 > 0.0f) ? sqrtf(fmaxf(var, 0.0f)) : 0.0f;

    // Deterministic block reduction (fixed-order shuffle tree).
    float v = dev;
    #pragma unroll
    for (int o = 16; o; o >>= 1) v += __shfl_xor_sync(0xffffffffu, v, o);

    __shared__ float wsum[(TH * TW) / 32];   // 16 warps
    if ((tid & 31) == 0) wsum[tid >> 5] = v;
    __syncthreads();

    if (tid < 16) {
        float w = wsum[tid];
        #pragma unroll
        for (int o = 8; o; o >>= 1) w += __shfl_xor_sync(0x0000ffffu, w, o, 16);
        if (tid == 0)
            g_blocksums[blockIdx.y * NBX + blockIdx.x] = w;
    }
}

__global__ void final_reduce_kernel(float* __restrict__ out) {
    const int tid = threadIdx.x;
    float s = 0.0f;
    for (int idx = tid; idx < NB; idx += 256) s += g_blocksums[idx];

    #pragma unroll
    for (int o = 16; o; o >>= 1) s += __shfl_xor_sync(0xffffffffu, s, o);

    __shared__ float ws[8];
    if ((tid & 31) == 0) ws[tid >> 5] = s;
    __syncthreads();

    if (tid < 8) {
        float w = ws[tid];
        #pragma unroll
        for (int o = 4; o; o >>= 1) w += __shfl_xor_sync(0x000000ffu, w, o, 8);
        if (tid == 0) out[0] = w * 100.0f;
    }
}

extern "C" void kernel_launch(void* const* d_in, const int* in_sizes, int n_in,
                              void* d_out, int out_size) {
    const float* depth = (const float*)d_in[0];   // depthin (1,1,480,640)
    // d_in[1] = gt, unused by the reference's hot path.
    float* out = (float*)d_out;

    dim3 grid(NBX, NBY);
    dim3 block(TW, TH);
    stdev_kernel<<<grid, block>>>(depth);
    final_reduce_kernel<<<1, 256>>>(out);
}